// round 2
// baseline (speedup 1.0000x reference)
#include <cuda_runtime.h>
#include <cuda_fp16.h>
#include <math.h>
#include <stdint.h>

// ---------------- problem constants ----------------
#define B_ROWS 32768
#define KH     1024
#define KH2    2048
#define G3     3072
#define KIN    256
#define LD_STATE 1040
#define C_HALF_DT 0.05f        // 0.5*dt
#define C_DT      0.1f         // dt
#define C_DT6     (0.1f/6.0f)  // dt/6

// ---------------- scratch (device globals; no allocs allowed) ----------------
__device__ __half g_W1h [KH  * KH2];
__device__ __half g_W2h [KH2 * KH ];
__device__ __half g_WihT[KIN * G3 ];
__device__ __half g_WhhT[KH  * G3 ];
__device__ __half g_xh  [(size_t)B_ROWS * KIN];
__device__ __half g_hwork[(size_t)B_ROWS * KH];
__device__ __half g_Z   [(size_t)B_ROWS * KH2];
__device__ float  g_ksum[(size_t)B_ROWS * KH];
__device__ float  g_htm [(size_t)B_ROWS * KH];
__device__ __half g_gi  [(size_t)B_ROWS * G3];
__device__ __half g_gh  [(size_t)B_ROWS * G3];
__device__ __half g_hnew[(size_t)B_ROWS * KH];

// ---------------- small helpers ----------------
__device__ __forceinline__ uint32_t smem_u32(const void* p) {
    return (uint32_t)__cvta_generic_to_shared(p);
}
__device__ __forceinline__ void cp_async16(void* smem, const void* gmem) {
    asm volatile("cp.async.cg.shared.global [%0], [%1], 16;\n"
                 :: "r"(smem_u32(smem)), "l"(gmem));
}
__device__ __forceinline__ void cp_commit() {
    asm volatile("cp.async.commit_group;\n");
}
__device__ __forceinline__ void ldsm_x4(uint32_t* r, uint32_t addr) {
    asm volatile("ldmatrix.sync.aligned.m8n8.x4.shared.b16 {%0,%1,%2,%3}, [%4];\n"
                 : "=r"(r[0]), "=r"(r[1]), "=r"(r[2]), "=r"(r[3]) : "r"(addr));
}
__device__ __forceinline__ void ldsm_x4_t(uint32_t* r, uint32_t addr) {
    asm volatile("ldmatrix.sync.aligned.m8n8.x4.trans.shared.b16 {%0,%1,%2,%3}, [%4];\n"
                 : "=r"(r[0]), "=r"(r[1]), "=r"(r[2]), "=r"(r[3]) : "r"(addr));
}
__device__ __forceinline__ void mma16816(float* d, const uint32_t* a, const uint32_t* b) {
    asm volatile("mma.sync.aligned.m16n8k16.row.col.f32.f16.f16.f32 "
                 "{%0,%1,%2,%3}, {%4,%5,%6,%7}, {%8,%9}, {%0,%1,%2,%3};\n"
                 : "+f"(d[0]), "+f"(d[1]), "+f"(d[2]), "+f"(d[3])
                 : "r"(a[0]), "r"(a[1]), "r"(a[2]), "r"(a[3]),
                   "r"(b[0]), "r"(b[1]));
}

// ---------------- generic fp16 GEMM with fused epilogues ----------------
// C[M,N] = A[M,K] @ B[K,N]  (A,B fp16 row-major, fp32 accumulate)
// mode 0: outh = fp16(tanh(C + bias))                (Z = tanh(h@W1+b1))
// mode 1: RK4 stage epilogue (stage 1..4), N==1024:
//         k = C + bias; ksum update; hwork = fp16(ht + c*k); stage4 -> htm fp32
// mode 2: outh = fp16(C + bias)                      (gi / gh)
#define BM 128
#define BN 128
#define BK 32
#define PAD 8

__device__ __forceinline__ void load_tile(
    const __half* __restrict__ A, const __half* __restrict__ Bm,
    int K, int N, int bm, int bn, int kb,
    __half (*as)[BK + PAD], __half (*bs)[BN + PAD], int tid)
{
    int arow = tid >> 2;           // 0..63
    int acol = (tid & 3) << 3;     // 0,8,16,24
    const __half* gA = A + (size_t)(bm + arow) * K + (size_t)kb * BK + acol;
    cp_async16(&as[arow][acol],      gA);
    cp_async16(&as[arow + 64][acol], gA + (size_t)64 * K);
    int brow = tid >> 4;           // 0..15
    int bcol = (tid & 15) << 3;    // 0..120
    const __half* gB = Bm + (size_t)((size_t)kb * BK + brow) * N + bn + bcol;
    cp_async16(&bs[brow][bcol],      gB);
    cp_async16(&bs[brow + 16][bcol], gB + (size_t)16 * N);
}

__global__ void __launch_bounds__(256) gemm16(
    const __half* __restrict__ A, const __half* __restrict__ Bm,
    int M, int N, int K, int mode, int stage,
    const float* __restrict__ bias, const float* __restrict__ state,
    float* __restrict__ ksum, __half* __restrict__ outh, float* __restrict__ outf)
{
    __shared__ __half As[2][BM][BK + PAD];
    __shared__ __half Bs[2][BK][BN + PAD];

    const int tid  = threadIdx.x;
    const int lane = tid & 31;
    const int warp = tid >> 5;
    const int wm   = warp >> 2;   // 0..1  (64 rows each)
    const int wn   = warp & 3;    // 0..3  (32 cols each)
    const int bn   = blockIdx.x * BN;
    const int bm   = blockIdx.y * BM;

    float acc[4][4][4];
#pragma unroll
    for (int mt = 0; mt < 4; mt++)
#pragma unroll
        for (int nt = 0; nt < 4; nt++)
#pragma unroll
            for (int i = 0; i < 4; i++) acc[mt][nt][i] = 0.f;

    const int nkb = K / BK;
    load_tile(A, Bm, K, N, bm, bn, 0, As[0], Bs[0], tid);
    cp_commit();

    for (int kb = 0; kb < nkb; kb++) {
        const int buf = kb & 1;
        if (kb + 1 < nkb) {
            load_tile(A, Bm, K, N, bm, bn, kb + 1, As[buf ^ 1], Bs[buf ^ 1], tid);
            cp_commit();
            asm volatile("cp.async.wait_group 1;\n");
        } else {
            asm volatile("cp.async.wait_group 0;\n");
        }
        __syncthreads();

        __half (*as)[BK + PAD] = As[buf];
        __half (*bs)[BN + PAD] = Bs[buf];

#pragma unroll
        for (int ks = 0; ks < 2; ks++) {
            uint32_t af[4][4];
#pragma unroll
            for (int mt = 0; mt < 4; mt++) {
                uint32_t addr = smem_u32(&as[wm * 64 + mt * 16 + (lane & 15)]
                                           [ks * 16 + ((lane >> 4) << 3)]);
                ldsm_x4(af[mt], addr);
            }
            uint32_t bf[4][2];
#pragma unroll
            for (int np = 0; np < 2; np++) {
                uint32_t r[4];
                uint32_t addr = smem_u32(&bs[ks * 16 + (lane & 15)]
                                           [wn * 32 + np * 16 + ((lane >> 4) << 3)]);
                ldsm_x4_t(r, addr);
                bf[np * 2][0]     = r[0]; bf[np * 2][1]     = r[1];
                bf[np * 2 + 1][0] = r[2]; bf[np * 2 + 1][1] = r[3];
            }
#pragma unroll
            for (int mt = 0; mt < 4; mt++)
#pragma unroll
                for (int nt = 0; nt < 4; nt++)
                    mma16816(acc[mt][nt], af[mt], bf[nt]);
        }
        __syncthreads();
    }

    // ---------------- epilogue ----------------
#pragma unroll
    for (int mt = 0; mt < 4; mt++) {
#pragma unroll
        for (int nt = 0; nt < 4; nt++) {
            int row = bm + wm * 64 + mt * 16 + (lane >> 2);
            int col = bn + wn * 32 + nt * 8 + ((lane & 3) << 1);
            float bc0 = bias[col], bc1 = bias[col + 1];
#pragma unroll
            for (int h = 0; h < 2; h++) {
                int r = row + h * 8;
                float v0 = acc[mt][nt][h * 2 + 0] + bc0;
                float v1 = acc[mt][nt][h * 2 + 1] + bc1;
                if (mode == 0) {
                    *reinterpret_cast<__half2*>(outh + (size_t)r * N + col) =
                        __floats2half2_rn(tanhf(v0), tanhf(v1));
                } else if (mode == 2) {
                    *reinterpret_cast<__half2*>(outh + (size_t)r * N + col) =
                        __floats2half2_rn(v0, v1);
                } else {
                    size_t idx = (size_t)r * N + col;   // N == 1024 here
                    float h0 = state[(size_t)r * LD_STATE + 16 + col];
                    float h1 = state[(size_t)r * LD_STATE + 16 + col + 1];
                    if (stage == 1) {
                        ksum[idx] = v0; ksum[idx + 1] = v1;
                        *reinterpret_cast<__half2*>(outh + idx) =
                            __floats2half2_rn(h0 + C_HALF_DT * v0, h1 + C_HALF_DT * v1);
                    } else if (stage == 2) {
                        ksum[idx] += 2.f * v0; ksum[idx + 1] += 2.f * v1;
                        *reinterpret_cast<__half2*>(outh + idx) =
                            __floats2half2_rn(h0 + C_HALF_DT * v0, h1 + C_HALF_DT * v1);
                    } else if (stage == 3) {
                        ksum[idx] += 2.f * v0; ksum[idx + 1] += 2.f * v1;
                        *reinterpret_cast<__half2*>(outh + idx) =
                            __floats2half2_rn(h0 + C_DT * v0, h1 + C_DT * v1);
                    } else {
                        float hn0 = h0 + C_DT6 * (ksum[idx] + v0);
                        float hn1 = h1 + C_DT6 * (ksum[idx + 1] + v1);
                        outf[idx] = hn0; outf[idx + 1] = hn1;
                        *reinterpret_cast<__half2*>(outh + idx) =
                            __floats2half2_rn(hn0, hn1);
                    }
                }
            }
        }
    }
}

// ---------------- elementwise / prep kernels ----------------
__global__ void cvt_f2h(const float* __restrict__ in, __half* __restrict__ out, int n) {
    int i = blockIdx.x * blockDim.x + threadIdx.x;
    int stride = gridDim.x * blockDim.x;
    for (; i < n; i += stride) out[i] = __float2half(in[i]);
}

// in: [R][C] row-major  ->  out: [C][R] row-major (transposed)
__global__ void tr_f2h(const float* __restrict__ in, __half* __restrict__ out, int R, int C) {
    int i = blockIdx.x * blockDim.x + threadIdx.x;
    int stride = gridDim.x * blockDim.x;
    int total = R * C;
    for (; i < total; i += stride) {
        int r = i / C, c = i % C;
        out[(size_t)c * R + r] = __float2half(in[i]);
    }
}

__global__ void extract_h(const float* __restrict__ state, __half* __restrict__ hw) {
    int i = blockIdx.x * blockDim.x + threadIdx.x;
    if (i >= B_ROWS * KH) return;
    int r = i >> 10, j = i & 1023;
    hw[i] = __float2half(state[(size_t)r * LD_STATE + 16 + j]);
}

__global__ void gates_kernel(const __half* __restrict__ gi, const __half* __restrict__ gh,
                             const float* __restrict__ htm, float* __restrict__ out,
                             __half* __restrict__ hnew) {
    int idx = blockIdx.x * blockDim.x + threadIdx.x;
    if (idx >= B_ROWS * KH) return;
    int r = idx >> 10, j = idx & 1023;
    size_t base = (size_t)r * G3;
    float ir = __half2float(gi[base + j]);
    float iz = __half2float(gi[base + 1024 + j]);
    float in_ = __half2float(gi[base + 2048 + j]);
    float hr = __half2float(gh[base + j]);
    float hz = __half2float(gh[base + 1024 + j]);
    float hn = __half2float(gh[base + 2048 + j]);
    float rr = 1.f / (1.f + expf(-(ir + hr)));
    float zz = 1.f / (1.f + expf(-(iz + hz)));
    float nn = tanhf(in_ + rr * hn);
    float h  = htm[idx];
    float res = (1.f - zz) * nn + zz * h;
    out[(size_t)r * LD_STATE + 16 + j] = res;
    hnew[idx] = __float2half(res);
}

// one warp per row: y[r, 0:16] = hnew[r,:] @ Wly + bly, masked by y_type
__global__ void ly_kernel(const __half* __restrict__ hnew, const float* __restrict__ Wly,
                          const float* __restrict__ bly, const int* __restrict__ y_type,
                          const float* __restrict__ state, float* __restrict__ out) {
    int gw = (blockIdx.x * blockDim.x + threadIdx.x) >> 5;
    int lane = threadIdx.x & 31;
    if (gw >= B_ROWS) return;
    const __half* hr = hnew + (size_t)gw * KH;
    float acc[16];
#pragma unroll
    for (int o = 0; o < 16; o++) acc[o] = 0.f;
    for (int k = lane; k < KH; k += 32) {
        float h = __half2float(hr[k]);
        const float4* w = reinterpret_cast<const float4*>(Wly + (size_t)k * 16);
#pragma unroll
        for (int q = 0; q < 4; q++) {
            float4 wv = w[q];
            acc[q * 4 + 0] += h * wv.x;
            acc[q * 4 + 1] += h * wv.y;
            acc[q * 4 + 2] += h * wv.z;
            acc[q * 4 + 3] += h * wv.w;
        }
    }
#pragma unroll
    for (int o = 0; o < 16; o++)
#pragma unroll
        for (int s = 16; s; s >>= 1) acc[o] += __shfl_xor_sync(0xffffffffu, acc[o], s);
    float v = 0.f;
#pragma unroll
    for (int o = 0; o < 16; o++) if (lane == o) v = acc[o] + bly[o];
    if (lane < 16) {
        float yv = (y_type[lane] == 0) ? v : state[(size_t)gw * LD_STATE + lane];
        out[(size_t)gw * LD_STATE + lane] = yv;
    }
}

// ---------------- launch ----------------
extern "C" void kernel_launch(void* const* d_in, const int* in_sizes, int n_in,
                              void* d_out, int out_size) {
    (void)in_sizes; (void)n_in; (void)out_size;
    const float* state = (const float*)d_in[0];
    const float* xt    = (const float*)d_in[1];
    const float* W1    = (const float*)d_in[2];
    const float* b1    = (const float*)d_in[3];
    const float* W2    = (const float*)d_in[4];
    const float* b2    = (const float*)d_in[5];
    const float* Wih   = (const float*)d_in[6];
    const float* Whh   = (const float*)d_in[7];
    const float* bih   = (const float*)d_in[8];
    const float* bhh   = (const float*)d_in[9];
    const float* Wly   = (const float*)d_in[10];
    const float* bly   = (const float*)d_in[11];
    const int*   y_type = (const int*)d_in[12];
    float* out = (float*)d_out;

    __half *W1h, *W2h, *WihT, *WhhT, *xh, *hwork, *Z, *gi, *gh, *hnew;
    float  *ksum, *htm;
    cudaGetSymbolAddress((void**)&W1h,  g_W1h);
    cudaGetSymbolAddress((void**)&W2h,  g_W2h);
    cudaGetSymbolAddress((void**)&WihT, g_WihT);
    cudaGetSymbolAddress((void**)&WhhT, g_WhhT);
    cudaGetSymbolAddress((void**)&xh,   g_xh);
    cudaGetSymbolAddress((void**)&hwork, g_hwork);
    cudaGetSymbolAddress((void**)&Z,    g_Z);
    cudaGetSymbolAddress((void**)&ksum, g_ksum);
    cudaGetSymbolAddress((void**)&htm,  g_htm);
    cudaGetSymbolAddress((void**)&gi,   g_gi);
    cudaGetSymbolAddress((void**)&gh,   g_gh);
    cudaGetSymbolAddress((void**)&hnew, g_hnew);

    const int TPB = 256;
    // weight prep (graph-captured once; trivial cost on replay)
    cvt_f2h<<<1024, TPB>>>(W1, W1h, KH * KH2);
    cvt_f2h<<<1024, TPB>>>(W2, W2h, KH2 * KH);
    cvt_f2h<<<1024, TPB>>>(xt, xh, B_ROWS * KIN);
    tr_f2h<<<1024, TPB>>>(Wih, WihT, G3, KIN);
    tr_f2h<<<1024, TPB>>>(Whh, WhhT, G3, KH);
    extract_h<<<(B_ROWS * KH + TPB - 1) / TPB, TPB>>>(state, hwork);

    // GRU input-gate GEMM (independent of RK4)
    gemm16<<<dim3(G3 / BN, B_ROWS / BM), TPB>>>(xh, WihT, B_ROWS, G3, KIN,
                                                2, 0, bih, nullptr, nullptr, gi, nullptr);
    // RK4: 4 stages, each = tanh GEMM then k GEMM with fused state update
    for (int s = 1; s <= 4; s++) {
        gemm16<<<dim3(KH2 / BN, B_ROWS / BM), TPB>>>(hwork, W1h, B_ROWS, KH2, KH,
                                                     0, 0, b1, nullptr, nullptr, Z, nullptr);
        gemm16<<<dim3(KH / BN, B_ROWS / BM), TPB>>>(Z, W2h, B_ROWS, KH, KH2,
                                                    1, s, b2, state, ksum, hwork, htm);
    }
    // GRU hidden-gate GEMM (hwork now holds fp16(ht_))
    gemm16<<<dim3(G3 / BN, B_ROWS / BM), TPB>>>(hwork, WhhT, B_ROWS, G3, KH,
                                                2, 0, bhh, nullptr, nullptr, gh, nullptr);
    // gates + output head
    gates_kernel<<<(B_ROWS * KH + TPB - 1) / TPB, TPB>>>(gi, gh, htm, out, hnew);
    ly_kernel<<<(B_ROWS * 32 + TPB - 1) / TPB, TPB>>>(hnew, Wly, bly, y_type, state, out);
}

// round 7
// speedup vs baseline: 1.0390x; 1.0390x over previous
#include <cuda_runtime.h>
#include <cuda_fp16.h>
#include <math.h>
#include <stdint.h>

// ---------------- problem constants ----------------
#define B_ROWS 32768
#define KH     1024
#define KH2    2048
#define G3     3072
#define KIN    256
#define LD_STATE 1040
#define C_HALF_DT 0.05f        // 0.5*dt
#define C_DT      0.1f         // dt
#define C_DT6     (0.1f/6.0f)  // dt/6

// ---------------- scratch (device globals; no allocs allowed) ----------------
__device__ __half g_W1h [KH  * KH2];
__device__ __half g_W2h [KH2 * KH ];
__device__ __half g_WihT[KIN * G3 ];
__device__ __half g_WhhT[KH  * G3 ];
__device__ __half g_xh  [(size_t)B_ROWS * KIN];
__device__ __half g_hwork[(size_t)B_ROWS * KH];
__device__ __half g_Z   [(size_t)B_ROWS * KH2];
__device__ float  g_ksum[(size_t)B_ROWS * KH];
__device__ float  g_htm [(size_t)B_ROWS * KH];
__device__ __half g_gi  [(size_t)B_ROWS * G3];
__device__ __half g_gh  [(size_t)B_ROWS * G3];
__device__ __half g_hnew[(size_t)B_ROWS * KH];

// ---------------- small helpers ----------------
__device__ __forceinline__ uint32_t smem_u32(const void* p) {
    return (uint32_t)__cvta_generic_to_shared(p);
}
__device__ __forceinline__ void cp_async16(void* smem, const void* gmem) {
    asm volatile("cp.async.cg.shared.global [%0], [%1], 16;\n"
                 :: "r"(smem_u32(smem)), "l"(gmem));
}
__device__ __forceinline__ void cp_commit() {
    asm volatile("cp.async.commit_group;\n");
}
__device__ __forceinline__ void ldsm_x4(uint32_t* r, uint32_t addr) {
    asm volatile("ldmatrix.sync.aligned.m8n8.x4.shared.b16 {%0,%1,%2,%3}, [%4];\n"
                 : "=r"(r[0]), "=r"(r[1]), "=r"(r[2]), "=r"(r[3]) : "r"(addr));
}
__device__ __forceinline__ void ldsm_x4_t(uint32_t* r, uint32_t addr) {
    asm volatile("ldmatrix.sync.aligned.m8n8.x4.trans.shared.b16 {%0,%1,%2,%3}, [%4];\n"
                 : "=r"(r[0]), "=r"(r[1]), "=r"(r[2]), "=r"(r[3]) : "r"(addr));
}
__device__ __forceinline__ void mma16816(float* d, const uint32_t* a, const uint32_t* b) {
    asm volatile("mma.sync.aligned.m16n8k16.row.col.f32.f16.f16.f32 "
                 "{%0,%1,%2,%3}, {%4,%5,%6,%7}, {%8,%9}, {%0,%1,%2,%3};\n"
                 : "+f"(d[0]), "+f"(d[1]), "+f"(d[2]), "+f"(d[3])
                 : "r"(a[0]), "r"(a[1]), "r"(a[2]), "r"(a[3]),
                   "r"(b[0]), "r"(b[1]));
}

// ---------------- generic fp16 GEMM with fused epilogues ----------------
// C[M,N] = A[M,K] @ B[K,N]  (A,B fp16 row-major, fp32 accumulate)
// mode 0: outh = fp16(tanh(C + bias))                (Z = tanh(h@W1+b1))
// mode 1: RK4 stage epilogue (stage 1..4), N==1024
// mode 2: outh = fp16(C + bias)                      (gi / gh)
#define BM 128
#define BN 128
#define BK 32
#define PAD 8

__device__ __forceinline__ void load_tile(
    const __half* __restrict__ A, const __half* __restrict__ Bm,
    int K, int N, int bm, int bn, int kb,
    __half (*as)[BK + PAD], __half (*bs)[BN + PAD], int tid)
{
    int arow = tid >> 2;           // 0..63
    int acol = (tid & 3) << 3;     // 0,8,16,24
    const __half* gA = A + (size_t)(bm + arow) * K + (size_t)kb * BK + acol;
    cp_async16(&as[arow][acol],      gA);
    cp_async16(&as[arow + 64][acol], gA + (size_t)64 * K);
    int brow = tid >> 4;           // 0..15
    int bcol = (tid & 15) << 3;    // 0..120
    const __half* gB = Bm + (size_t)((size_t)kb * BK + brow) * N + bn + bcol;
    cp_async16(&bs[brow][bcol],      gB);
    cp_async16(&bs[brow + 16][bcol], gB + (size_t)16 * N);
}

__global__ void __launch_bounds__(256, 2) gemm16(
    const __half* __restrict__ A, const __half* __restrict__ Bm,
    int M, int N, int K, int mode, int stage,
    const float* __restrict__ bias, const float* __restrict__ state,
    float* __restrict__ ksum, __half* __restrict__ outh, float* __restrict__ outf)
{
    __shared__ __half As[2][BM][BK + PAD];
    __shared__ __half Bs[2][BK][BN + PAD];

    const int tid  = threadIdx.x;
    const int lane = tid & 31;
    const int warp = tid >> 5;
    const int wm   = warp >> 2;   // 0..1  (64 rows each)
    const int wn   = warp & 3;    // 0..3  (32 cols each)
    const int bn   = blockIdx.x * BN;
    const int bm   = blockIdx.y * BM;

    float acc[4][4][4];
#pragma unroll
    for (int mt = 0; mt < 4; mt++)
#pragma unroll
        for (int nt = 0; nt < 4; nt++)
#pragma unroll
            for (int i = 0; i < 4; i++) acc[mt][nt][i] = 0.f;

    const int nkb = K / BK;
    load_tile(A, Bm, K, N, bm, bn, 0, As[0], Bs[0], tid);
    cp_commit();

    for (int kb = 0; kb < nkb; kb++) {
        const int buf = kb & 1;
        if (kb + 1 < nkb) {
            load_tile(A, Bm, K, N, bm, bn, kb + 1, As[buf ^ 1], Bs[buf ^ 1], tid);
            cp_commit();
            asm volatile("cp.async.wait_group 1;\n");
        } else {
            asm volatile("cp.async.wait_group 0;\n");
        }
        __syncthreads();

        __half (*as)[BK + PAD] = As[buf];
        __half (*bs)[BN + PAD] = Bs[buf];

#pragma unroll
        for (int ks = 0; ks < 2; ks++) {
            uint32_t af[4][4];
#pragma unroll
            for (int mt = 0; mt < 4; mt++) {
                uint32_t addr = smem_u32(&as[wm * 64 + mt * 16 + (lane & 15)]
                                           [ks * 16 + ((lane >> 4) << 3)]);
                ldsm_x4(af[mt], addr);
            }
            uint32_t bf[4][2];
#pragma unroll
            for (int np = 0; np < 2; np++) {
                uint32_t r[4];
                uint32_t addr = smem_u32(&bs[ks * 16 + (lane & 15)]
                                           [wn * 32 + np * 16 + ((lane >> 4) << 3)]);
                ldsm_x4_t(r, addr);
                bf[np * 2][0]     = r[0]; bf[np * 2][1]     = r[1];
                bf[np * 2 + 1][0] = r[2]; bf[np * 2 + 1][1] = r[3];
            }
#pragma unroll
            for (int mt = 0; mt < 4; mt++)
#pragma unroll
                for (int nt = 0; nt < 4; nt++)
                    mma16816(acc[mt][nt], af[mt], bf[nt]);
        }
        __syncthreads();
    }

    // ---------------- epilogue ----------------
#pragma unroll
    for (int mt = 0; mt < 4; mt++) {
#pragma unroll
        for (int nt = 0; nt < 4; nt++) {
            int row = bm + wm * 64 + mt * 16 + (lane >> 2);
            int col = bn + wn * 32 + nt * 8 + ((lane & 3) << 1);
            float bc0 = bias[col], bc1 = bias[col + 1];
#pragma unroll
            for (int h = 0; h < 2; h++) {
                int r = row + h * 8;
                float v0 = acc[mt][nt][h * 2 + 0] + bc0;
                float v1 = acc[mt][nt][h * 2 + 1] + bc1;
                if (mode == 0) {
                    *reinterpret_cast<__half2*>(outh + (size_t)r * N + col) =
                        __floats2half2_rn(tanhf(v0), tanhf(v1));
                } else if (mode == 2) {
                    *reinterpret_cast<__half2*>(outh + (size_t)r * N + col) =
                        __floats2half2_rn(v0, v1);
                } else {
                    size_t idx = (size_t)r * N + col;   // N == 1024 here
                    float h0 = state[(size_t)r * LD_STATE + 16 + col];
                    float h1 = state[(size_t)r * LD_STATE + 16 + col + 1];
                    if (stage == 1) {
                        ksum[idx] = v0; ksum[idx + 1] = v1;
                        *reinterpret_cast<__half2*>(outh + idx) =
                            __floats2half2_rn(h0 + C_HALF_DT * v0, h1 + C_HALF_DT * v1);
                    } else if (stage == 2) {
                        ksum[idx] += 2.f * v0; ksum[idx + 1] += 2.f * v1;
                        *reinterpret_cast<__half2*>(outh + idx) =
                            __floats2half2_rn(h0 + C_HALF_DT * v0, h1 + C_HALF_DT * v1);
                    } else if (stage == 3) {
                        ksum[idx] += 2.f * v0; ksum[idx + 1] += 2.f * v1;
                        *reinterpret_cast<__half2*>(outh + idx) =
                            __floats2half2_rn(h0 + C_DT * v0, h1 + C_DT * v1);
                    } else {
                        float hn0 = h0 + C_DT6 * (ksum[idx] + v0);
                        float hn1 = h1 + C_DT6 * (ksum[idx + 1] + v1);
                        outf[idx] = hn0; outf[idx + 1] = hn1;
                        *reinterpret_cast<__half2*>(outh + idx) =
                            __floats2half2_rn(hn0, hn1);
                    }
                }
            }
        }
    }
}

// ---------------- elementwise / prep kernels ----------------
__global__ void cvt_f2h(const float* __restrict__ in, __half* __restrict__ out, int n) {
    int i = blockIdx.x * blockDim.x + threadIdx.x;
    int stride = gridDim.x * blockDim.x;
    for (; i < n; i += stride) out[i] = __float2half(in[i]);
}

// in: [R][C] row-major  ->  out: [C][R] row-major (transposed)
__global__ void tr_f2h(const float* __restrict__ in, __half* __restrict__ out, int R, int C) {
    int i = blockIdx.x * blockDim.x + threadIdx.x;
    int stride = gridDim.x * blockDim.x;
    int total = R * C;
    for (; i < total; i += stride) {
        int r = i / C, c = i % C;
        out[(size_t)c * R + r] = __float2half(in[i]);
    }
}

__global__ void extract_h(const float* __restrict__ state, __half* __restrict__ hw) {
    int i = blockIdx.x * blockDim.x + threadIdx.x;
    if (i >= B_ROWS * KH) return;
    int r = i >> 10, j = i & 1023;
    hw[i] = __float2half(state[(size_t)r * LD_STATE + 16 + j]);
}

__global__ void gates_kernel(const __half* __restrict__ gi, const __half* __restrict__ gh,
                             const float* __restrict__ htm, float* __restrict__ out,
                             __half* __restrict__ hnew) {
    int idx = blockIdx.x * blockDim.x + threadIdx.x;
    if (idx >= B_ROWS * KH) return;
    int r = idx >> 10, j = idx & 1023;
    size_t base = (size_t)r * G3;
    float ir  = __half2float(gi[base + j]);
    float iz  = __half2float(gi[base + 1024 + j]);
    float in_ = __half2float(gi[base + 2048 + j]);
    float hr  = __half2float(gh[base + j]);
    float hz  = __half2float(gh[base + 1024 + j]);
    float hn  = __half2float(gh[base + 2048 + j]);
    float rr = 1.f / (1.f + expf(-(ir + hr)));
    float zz = 1.f / (1.f + expf(-(iz + hz)));
    float nn = tanhf(in_ + rr * hn);
    float h  = htm[idx];
    float res = (1.f - zz) * nn + zz * h;
    out[(size_t)r * LD_STATE + 16 + j] = res;
    hnew[idx] = __float2half(res);
}

// one warp per row: y[r, 0:16] = hnew[r,:] @ Wly + bly, masked by y_type
__global__ void ly_kernel(const __half* __restrict__ hnew, const float* __restrict__ Wly,
                          const float* __restrict__ bly, const int* __restrict__ y_type,
                          const float* __restrict__ state, float* __restrict__ out) {
    int gw = (blockIdx.x * blockDim.x + threadIdx.x) >> 5;
    int lane = threadIdx.x & 31;
    if (gw >= B_ROWS) return;
    const __half* hr = hnew + (size_t)gw * KH;
    float acc[16];
#pragma unroll
    for (int o = 0; o < 16; o++) acc[o] = 0.f;
    for (int k = lane; k < KH; k += 32) {
        float h = __half2float(hr[k]);
        const float4* w = reinterpret_cast<const float4*>(Wly + (size_t)k * 16);
#pragma unroll
        for (int q = 0; q < 4; q++) {
            float4 wv = w[q];
            acc[q * 4 + 0] += h * wv.x;
            acc[q * 4 + 1] += h * wv.y;
            acc[q * 4 + 2] += h * wv.z;
            acc[q * 4 + 3] += h * wv.w;
        }
    }
#pragma unroll
    for (int o = 0; o < 16; o++)
#pragma unroll
        for (int s = 16; s; s >>= 1) acc[o] += __shfl_xor_sync(0xffffffffu, acc[o], s);
    // lane o holds the reduced acc[o]; select own output via shuffle of packed values
    if (lane < 16) {
        float v = acc[lane] + bly[lane];   // acc[lane] is fully reduced on every lane
        float yv = (y_type[lane] == 0) ? v : state[(size_t)gw * LD_STATE + lane];
        out[(size_t)gw * LD_STATE + lane] = yv;
    }
}

// ---------------- launch ----------------
extern "C" void kernel_launch(void* const* d_in, const int* in_sizes, int n_in,
                              void* d_out, int out_size) {
    (void)in_sizes; (void)n_in; (void)out_size;
    const float* state = (const float*)d_in[0];
    const float* xt    = (const float*)d_in[1];
    const float* W1    = (const float*)d_in[2];
    const float* b1    = (const float*)d_in[3];
    const float* W2    = (const float*)d_in[4];
    const float* b2    = (const float*)d_in[5];
    const float* Wih   = (const float*)d_in[6];
    const float* Whh   = (const float*)d_in[7];
    const float* bih   = (const float*)d_in[8];
    const float* bhh   = (const float*)d_in[9];
    const float* Wly   = (const float*)d_in[10];
    const float* bly   = (const float*)d_in[11];
    const int*   y_type = (const int*)d_in[12];
    float* out = (float*)d_out;

    __half *W1h, *W2h, *WihT, *WhhT, *xh, *hwork, *Z, *gi, *gh, *hnew;
    float  *ksum, *htm;
    cudaGetSymbolAddress((void**)&W1h,  g_W1h);
    cudaGetSymbolAddress((void**)&W2h,  g_W2h);
    cudaGetSymbolAddress((void**)&WihT, g_WihT);
    cudaGetSymbolAddress((void**)&WhhT, g_WhhT);
    cudaGetSymbolAddress((void**)&xh,   g_xh);
    cudaGetSymbolAddress((void**)&hwork, g_hwork);
    cudaGetSymbolAddress((void**)&Z,    g_Z);
    cudaGetSymbolAddress((void**)&ksum, g_ksum);
    cudaGetSymbolAddress((void**)&htm,  g_htm);
    cudaGetSymbolAddress((void**)&gi,   g_gi);
    cudaGetSymbolAddress((void**)&gh,   g_gh);
    cudaGetSymbolAddress((void**)&hnew, g_hnew);

    const int TPB = 256;
    // weight prep (graph-captured once; trivial cost on replay)
    cvt_f2h<<<1024, TPB>>>(W1, W1h, KH * KH2);
    cvt_f2h<<<1024, TPB>>>(W2, W2h, KH2 * KH);
    cvt_f2h<<<1024, TPB>>>(xt, xh, B_ROWS * KIN);
    tr_f2h<<<1024, TPB>>>(Wih, WihT, G3, KIN);
    tr_f2h<<<1024, TPB>>>(Whh, WhhT, G3, KH);
    extract_h<<<(B_ROWS * KH + TPB - 1) / TPB, TPB>>>(state, hwork);

    // GRU input-gate GEMM (independent of RK4)
    gemm16<<<dim3(G3 / BN, B_ROWS / BM), TPB>>>(xh, WihT, B_ROWS, G3, KIN,
                                                2, 0, bih, nullptr, nullptr, gi, nullptr);
    // RK4: 4 stages, each = tanh GEMM then k GEMM with fused state update
    for (int s = 1; s <= 4; s++) {
        gemm16<<<dim3(KH2 / BN, B_ROWS / BM), TPB>>>(hwork, W1h, B_ROWS, KH2, KH,
                                                     0, 0, b1, nullptr, nullptr, Z, nullptr);
        gemm16<<<dim3(KH / BN, B_ROWS / BM), TPB>>>(Z, W2h, B_ROWS, KH, KH2,
                                                    1, s, b2, state, ksum, hwork, htm);
    }
    // GRU hidden-gate GEMM (hwork now holds fp16(ht_))
    gemm16<<<dim3(G3 / BN, B_ROWS / BM), TPB>>>(hwork, WhhT, B_ROWS, G3, KH,
                                                2, 0, bhh, nullptr, nullptr, gh, nullptr);
    // gates + output head
    gates_kernel<<<(B_ROWS * KH + TPB - 1) / TPB, TPB>>>(gi, gh, htm, out, hnew);
    ly_kernel<<<(B_ROWS * 32 + TPB - 1) / TPB, TPB>>>(hnew, Wly, bly, y_type, state, out);
}

// round 10
// speedup vs baseline: 1.0850x; 1.0442x over previous
#include <cuda_runtime.h>
#include <cuda_fp16.h>
#include <math.h>
#include <stdint.h>

// ---------------- problem constants ----------------
#define B_ROWS 32768
#define KH     1024
#define KH2    2048
#define G3     3072
#define KIN    256
#define LD_STATE 1040
#define C_HALF_DT 0.05f        // 0.5*dt
#define C_DT      0.1f         // dt
#define C_DT6     (0.1f/6.0f)  // dt/6

// ---------------- scratch (device globals; no allocs allowed) ----------------
__device__ __half g_W1h [KH  * KH2];
__device__ __half g_W2h [KH2 * KH ];
__device__ __half g_WihT[KIN * G3 ];
__device__ __half g_WhhT[KH  * G3 ];
__device__ __half g_xh  [(size_t)B_ROWS * KIN];
__device__ __half g_hwork[(size_t)B_ROWS * KH];
__device__ __half g_Z   [(size_t)B_ROWS * KH2];
__device__ float  g_ksum[(size_t)B_ROWS * KH];
__device__ float  g_htm [(size_t)B_ROWS * KH];
__device__ __half g_gi  [(size_t)B_ROWS * G3];
__device__ __half g_gh  [(size_t)B_ROWS * G3];
__device__ __half g_hnew[(size_t)B_ROWS * KH];

// ---------------- small helpers ----------------
__device__ __forceinline__ uint32_t smem_u32(const void* p) {
    return (uint32_t)__cvta_generic_to_shared(p);
}
__device__ __forceinline__ void cp_async16(void* smem, const void* gmem) {
    asm volatile("cp.async.cg.shared.global [%0], [%1], 16;\n"
                 :: "r"(smem_u32(smem)), "l"(gmem));
}
__device__ __forceinline__ void cp_commit() {
    asm volatile("cp.async.commit_group;\n");
}
__device__ __forceinline__ void ldsm_x4(uint32_t* r, uint32_t addr) {
    asm volatile("ldmatrix.sync.aligned.m8n8.x4.shared.b16 {%0,%1,%2,%3}, [%4];\n"
                 : "=r"(r[0]), "=r"(r[1]), "=r"(r[2]), "=r"(r[3]) : "r"(addr));
}
__device__ __forceinline__ void ldsm_x4_t(uint32_t* r, uint32_t addr) {
    asm volatile("ldmatrix.sync.aligned.m8n8.x4.trans.shared.b16 {%0,%1,%2,%3}, [%4];\n"
                 : "=r"(r[0]), "=r"(r[1]), "=r"(r[2]), "=r"(r[3]) : "r"(addr));
}
__device__ __forceinline__ void mma16816(float* d, const uint32_t* a, const uint32_t* b) {
    asm volatile("mma.sync.aligned.m16n8k16.row.col.f32.f16.f16.f32 "
                 "{%0,%1,%2,%3}, {%4,%5,%6,%7}, {%8,%9}, {%0,%1,%2,%3};\n"
                 : "+f"(d[0]), "+f"(d[1]), "+f"(d[2]), "+f"(d[3])
                 : "r"(a[0]), "r"(a[1]), "r"(a[2]), "r"(a[3]),
                   "r"(b[0]), "r"(b[1]));
}

// ---------------- generic fp16 GEMM with fused epilogues ----------------
// C[M,N] = A[M,K] @ B[K,N]  (A,B fp16 row-major, fp32 accumulate)
// 128x128 block tile, 4 warps, 64x64 per warp (2x2 warp grid).
// mode 0: outh = fp16(tanh(C + bias))                (Z = tanh(h@W1+b1))
// mode 1: RK4 stage epilogue (stage 1..4), N==1024
// mode 2: outh = fp16(C + bias)                      (gi / gh)
#define BM 128
#define BN 128
#define BK 32
#define PAD 8
#define TPBG 128

__device__ __forceinline__ void load_tile(
    const __half* __restrict__ A, const __half* __restrict__ Bm,
    int K, int N, int bm, int bn, int kb,
    __half (*as)[BK + PAD], __half (*bs)[BN + PAD], int tid)
{
    int arow = tid >> 2;           // 0..31
    int acol = (tid & 3) << 3;     // 0,8,16,24
    const __half* gA = A + (size_t)(bm + arow) * K + (size_t)kb * BK + acol;
#pragma unroll
    for (int r = 0; r < 4; r++)
        cp_async16(&as[arow + 32 * r][acol], gA + (size_t)(32 * r) * K);
    int brow = tid >> 4;           // 0..7
    int bcol = (tid & 15) << 3;    // 0..120
    const __half* gB = Bm + (size_t)((size_t)kb * BK + brow) * N + bn + bcol;
#pragma unroll
    for (int r = 0; r < 4; r++)
        cp_async16(&bs[brow + 8 * r][bcol], gB + (size_t)(8 * r) * N);
}

__global__ void __launch_bounds__(TPBG, 2) gemm16(
    const __half* __restrict__ A, const __half* __restrict__ Bm,
    int M, int N, int K, int mode, int stage,
    const float* __restrict__ bias, const float* __restrict__ state,
    float* __restrict__ ksum, __half* __restrict__ outh, float* __restrict__ outf)
{
    __shared__ __half As[2][BM][BK + PAD];
    __shared__ __half Bs[2][BK][BN + PAD];

    const int tid  = threadIdx.x;
    const int lane = tid & 31;
    const int warp = tid >> 5;     // 0..3
    const int wm   = warp >> 1;    // 0..1 (64 rows each)
    const int wn   = warp & 1;     // 0..1 (64 cols each)
    const int bn   = blockIdx.x * BN;
    const int bm   = blockIdx.y * BM;

    float acc[4][8][4];
#pragma unroll
    for (int mt = 0; mt < 4; mt++)
#pragma unroll
        for (int nt = 0; nt < 8; nt++)
#pragma unroll
            for (int i = 0; i < 4; i++) acc[mt][nt][i] = 0.f;

    const int nkb = K / BK;
    load_tile(A, Bm, K, N, bm, bn, 0, As[0], Bs[0], tid);
    cp_commit();

    for (int kb = 0; kb < nkb; kb++) {
        const int buf = kb & 1;
        if (kb + 1 < nkb) {
            load_tile(A, Bm, K, N, bm, bn, kb + 1, As[buf ^ 1], Bs[buf ^ 1], tid);
            cp_commit();
            asm volatile("cp.async.wait_group 1;\n");
        } else {
            asm volatile("cp.async.wait_group 0;\n");
        }
        __syncthreads();

        __half (*as)[BK + PAD] = As[buf];
        __half (*bs)[BN + PAD] = Bs[buf];

#pragma unroll
        for (int ks = 0; ks < 2; ks++) {
            uint32_t af[4][4];
#pragma unroll
            for (int mt = 0; mt < 4; mt++) {
                uint32_t addr = smem_u32(&as[wm * 64 + mt * 16 + (lane & 15)]
                                           [ks * 16 + ((lane >> 4) << 3)]);
                ldsm_x4(af[mt], addr);
            }
            uint32_t bf[8][2];
#pragma unroll
            for (int np = 0; np < 4; np++) {
                uint32_t r[4];
                uint32_t addr = smem_u32(&bs[ks * 16 + (lane & 15)]
                                           [wn * 64 + np * 16 + ((lane >> 4) << 3)]);
                ldsm_x4_t(r, addr);
                bf[np * 2][0]     = r[0]; bf[np * 2][1]     = r[1];
                bf[np * 2 + 1][0] = r[2]; bf[np * 2 + 1][1] = r[3];
            }
#pragma unroll
            for (int mt = 0; mt < 4; mt++)
#pragma unroll
                for (int nt = 0; nt < 8; nt++)
                    mma16816(acc[mt][nt], af[mt], bf[nt]);
        }
        __syncthreads();
    }

    // ---------------- epilogue ----------------
#pragma unroll
    for (int mt = 0; mt < 4; mt++) {
#pragma unroll
        for (int nt = 0; nt < 8; nt++) {
            int row = bm + wm * 64 + mt * 16 + (lane >> 2);
            int col = bn + wn * 64 + nt * 8 + ((lane & 3) << 1);
            float bc0 = bias[col], bc1 = bias[col + 1];
#pragma unroll
            for (int h = 0; h < 2; h++) {
                int r = row + h * 8;
                float v0 = acc[mt][nt][h * 2 + 0] + bc0;
                float v1 = acc[mt][nt][h * 2 + 1] + bc1;
                if (mode == 0) {
                    *reinterpret_cast<__half2*>(outh + (size_t)r * N + col) =
                        __floats2half2_rn(tanhf(v0), tanhf(v1));
                } else if (mode == 2) {
                    *reinterpret_cast<__half2*>(outh + (size_t)r * N + col) =
                        __floats2half2_rn(v0, v1);
                } else {
                    size_t idx = (size_t)r * N + col;   // N == 1024 here
                    float h0 = state[(size_t)r * LD_STATE + 16 + col];
                    float h1 = state[(size_t)r * LD_STATE + 16 + col + 1];
                    if (stage == 1) {
                        ksum[idx] = v0; ksum[idx + 1] = v1;
                        *reinterpret_cast<__half2*>(outh + idx) =
                            __floats2half2_rn(h0 + C_HALF_DT * v0, h1 + C_HALF_DT * v1);
                    } else if (stage == 2) {
                        ksum[idx] += 2.f * v0; ksum[idx + 1] += 2.f * v1;
                        *reinterpret_cast<__half2*>(outh + idx) =
                            __floats2half2_rn(h0 + C_HALF_DT * v0, h1 + C_HALF_DT * v1);
                    } else if (stage == 3) {
                        ksum[idx] += 2.f * v0; ksum[idx + 1] += 2.f * v1;
                        *reinterpret_cast<__half2*>(outh + idx) =
                            __floats2half2_rn(h0 + C_DT * v0, h1 + C_DT * v1);
                    } else {
                        float hn0 = h0 + C_DT6 * (ksum[idx] + v0);
                        float hn1 = h1 + C_DT6 * (ksum[idx + 1] + v1);
                        outf[idx] = hn0; outf[idx + 1] = hn1;
                        *reinterpret_cast<__half2*>(outh + idx) =
                            __floats2half2_rn(hn0, hn1);
                    }
                }
            }
        }
    }
}

// ---------------- elementwise / prep kernels ----------------
__global__ void cvt_f2h(const float* __restrict__ in, __half* __restrict__ out, int n) {
    int i = blockIdx.x * blockDim.x + threadIdx.x;
    int stride = gridDim.x * blockDim.x;
    for (; i < n; i += stride) out[i] = __float2half(in[i]);
}

// in: [R][C] row-major  ->  out: [C][R] row-major (transposed)
__global__ void tr_f2h(const float* __restrict__ in, __half* __restrict__ out, int R, int C) {
    int i = blockIdx.x * blockDim.x + threadIdx.x;
    int stride = gridDim.x * blockDim.x;
    int total = R * C;
    for (; i < total; i += stride) {
        int r = i / C, c = i % C;
        out[(size_t)c * R + r] = __float2half(in[i]);
    }
}

__global__ void extract_h(const float* __restrict__ state, __half* __restrict__ hw) {
    int i = blockIdx.x * blockDim.x + threadIdx.x;
    if (i >= B_ROWS * KH) return;
    int r = i >> 10, j = i & 1023;
    hw[i] = __float2half(state[(size_t)r * LD_STATE + 16 + j]);
}

__global__ void gates_kernel(const __half* __restrict__ gi, const __half* __restrict__ gh,
                             const float* __restrict__ htm, float* __restrict__ out,
                             __half* __restrict__ hnew) {
    int idx = blockIdx.x * blockDim.x + threadIdx.x;
    if (idx >= B_ROWS * KH) return;
    int r = idx >> 10, j = idx & 1023;
    size_t base = (size_t)r * G3;
    float ir  = __half2float(gi[base + j]);
    float iz  = __half2float(gi[base + 1024 + j]);
    float in_ = __half2float(gi[base + 2048 + j]);
    float hr  = __half2float(gh[base + j]);
    float hz  = __half2float(gh[base + 1024 + j]);
    float hn  = __half2float(gh[base + 2048 + j]);
    float rr = 1.f / (1.f + expf(-(ir + hr)));
    float zz = 1.f / (1.f + expf(-(iz + hz)));
    float nn = tanhf(in_ + rr * hn);
    float h  = htm[idx];
    float res = (1.f - zz) * nn + zz * h;
    out[(size_t)r * LD_STATE + 16 + j] = res;
    hnew[idx] = __float2half(res);
}

// one warp per row: y[r, 0:16] = hnew[r,:] @ Wly + bly, masked by y_type
__global__ void ly_kernel(const __half* __restrict__ hnew, const float* __restrict__ Wly,
                          const float* __restrict__ bly, const int* __restrict__ y_type,
                          const float* __restrict__ state, float* __restrict__ out) {
    int gw = (blockIdx.x * blockDim.x + threadIdx.x) >> 5;
    int lane = threadIdx.x & 31;
    if (gw >= B_ROWS) return;
    const __half* hr = hnew + (size_t)gw * KH;
    float acc[16];
#pragma unroll
    for (int o = 0; o < 16; o++) acc[o] = 0.f;
    for (int k = lane; k < KH; k += 32) {
        float h = __half2float(hr[k]);
        const float4* w = reinterpret_cast<const float4*>(Wly + (size_t)k * 16);
#pragma unroll
        for (int q = 0; q < 4; q++) {
            float4 wv = w[q];
            acc[q * 4 + 0] += h * wv.x;
            acc[q * 4 + 1] += h * wv.y;
            acc[q * 4 + 2] += h * wv.z;
            acc[q * 4 + 3] += h * wv.w;
        }
    }
#pragma unroll
    for (int o = 0; o < 16; o++)
#pragma unroll
        for (int s = 16; s; s >>= 1) acc[o] += __shfl_xor_sync(0xffffffffu, acc[o], s);
    if (lane < 16) {
        float v = acc[lane] + bly[lane];   // acc[lane] fully reduced on every lane
        float yv = (y_type[lane] == 0) ? v : state[(size_t)gw * LD_STATE + lane];
        out[(size_t)gw * LD_STATE + lane] = yv;
    }
}

// ---------------- launch ----------------
extern "C" void kernel_launch(void* const* d_in, const int* in_sizes, int n_in,
                              void* d_out, int out_size) {
    (void)in_sizes; (void)n_in; (void)out_size;
    const float* state = (const float*)d_in[0];
    const float* xt    = (const float*)d_in[1];
    const float* W1    = (const float*)d_in[2];
    const float* b1    = (const float*)d_in[3];
    const float* W2    = (const float*)d_in[4];
    const float* b2    = (const float*)d_in[5];
    const float* Wih   = (const float*)d_in[6];
    const float* Whh   = (const float*)d_in[7];
    const float* bih   = (const float*)d_in[8];
    const float* bhh   = (const float*)d_in[9];
    const float* Wly   = (const float*)d_in[10];
    const float* bly   = (const float*)d_in[11];
    const int*   y_type = (const int*)d_in[12];
    float* out = (float*)d_out;

    __half *W1h, *W2h, *WihT, *WhhT, *xh, *hwork, *Z, *gi, *gh, *hnew;
    float  *ksum, *htm;
    cudaGetSymbolAddress((void**)&W1h,  g_W1h);
    cudaGetSymbolAddress((void**)&W2h,  g_W2h);
    cudaGetSymbolAddress((void**)&WihT, g_WihT);
    cudaGetSymbolAddress((void**)&WhhT, g_WhhT);
    cudaGetSymbolAddress((void**)&xh,   g_xh);
    cudaGetSymbolAddress((void**)&hwork, g_hwork);
    cudaGetSymbolAddress((void**)&Z,    g_Z);
    cudaGetSymbolAddress((void**)&ksum, g_ksum);
    cudaGetSymbolAddress((void**)&htm,  g_htm);
    cudaGetSymbolAddress((void**)&gi,   g_gi);
    cudaGetSymbolAddress((void**)&gh,   g_gh);
    cudaGetSymbolAddress((void**)&hnew, g_hnew);

    const int TPB = 256;
    // weight prep (graph-captured once; trivial cost on replay)
    cvt_f2h<<<1024, TPB>>>(W1, W1h, KH * KH2);
    cvt_f2h<<<1024, TPB>>>(W2, W2h, KH2 * KH);
    cvt_f2h<<<1024, TPB>>>(xt, xh, B_ROWS * KIN);
    tr_f2h<<<1024, TPB>>>(Wih, WihT, G3, KIN);
    tr_f2h<<<1024, TPB>>>(Whh, WhhT, G3, KH);
    extract_h<<<(B_ROWS * KH + TPB - 1) / TPB, TPB>>>(state, hwork);

    // GRU input-gate GEMM (independent of RK4)
    gemm16<<<dim3(G3 / BN, B_ROWS / BM), TPBG>>>(xh, WihT, B_ROWS, G3, KIN,
                                                 2, 0, bih, nullptr, nullptr, gi, nullptr);
    // RK4: 4 stages, each = tanh GEMM then k GEMM with fused state update
    for (int s = 1; s <= 4; s++) {
        gemm16<<<dim3(KH2 / BN, B_ROWS / BM), TPBG>>>(hwork, W1h, B_ROWS, KH2, KH,
                                                      0, 0, b1, nullptr, nullptr, Z, nullptr);
        gemm16<<<dim3(KH / BN, B_ROWS / BM), TPBG>>>(Z, W2h, B_ROWS, KH, KH2,
                                                     1, s, b2, state, ksum, hwork, htm);
    }
    // GRU hidden-gate GEMM (hwork now holds fp16(ht_))
    gemm16<<<dim3(G3 / BN, B_ROWS / BM), TPBG>>>(hwork, WhhT, B_ROWS, G3, KH,
                                                 2, 0, bhh, nullptr, nullptr, gh, nullptr);
    // gates + output head
    gates_kernel<<<(B_ROWS * KH + TPB - 1) / TPB, TPB>>>(gi, gh, htm, out, hnew);
    ly_kernel<<<(B_ROWS * 32 + TPB - 1) / TPB, TPB>>>(hnew, Wly, bly, y_type, state, out);
}